// round 14
// baseline (speedup 1.0000x reference)
#include <cuda_runtime.h>
#include <cuda_fp16.h>
#include <math.h>
#include <float.h>

#define NN 50000
#define EE 1600000
#define BB 64
#define HID 128
#define LAYERS 3
#define SCAN_BLK 1024
#define NSB ((NN + SCAN_BLK - 1) / SCAN_BLK)
#define STRH 136   // padded smem row stride in halves (272B)

typedef unsigned long long ull;

// ---------------- device scratch ----------------
__device__ __align__(256) float  d_h[NN * HID];
__device__ __align__(256) __half d_h16[NN * HID];
__device__ __align__(256) __half d_hhh[NN * HID];
__device__ __align__(256) unsigned char d_hh8[NN * HID];
__device__ __align__(256) __half d_w16[LAYERS * HID * HID];
__device__ __align__(16)  float  d_as[NN * 4];
__device__ __align__(16)  float  d_ad[NN * 4];
__device__ __align__(256) __half d_pre0[EE * 4];
__device__ __align__(256) __half d_pre1[EE * 4];
__device__ __align__(256) __half d_pre2[EE * 4];
__device__ __align__(256) float4 d_ea[EE];
__device__ __align__(16)  float4 d_loop[LAYERS * NN];
__device__ int d_deg[NN];
__device__ int d_off[NN + 1];
__device__ int d_cur[NN];
__device__ int d_csr_src[EE];
__device__ int d_btot[NSB];
__device__ __align__(16) float d_wepf[768];
__device__ float d_pool_sum[BB * HID];
__device__ unsigned d_pool_max[BB * HID];
__device__ int d_pool_cnt[BB];

__constant__ __align__(16) float c_eew[256];
__constant__ __align__(16) float c_eeb[64];
__constant__ __align__(16) ull   c_wep[32 * 12];

// ---------------- helpers ----------------
__device__ __forceinline__ float gelu_f(float x) {
    return 0.5f * x * (1.0f + erff(x * 0.70710678118654752f));
}
__device__ __forceinline__ unsigned fmap(float f) {
    unsigned u = __float_as_uint(f);
    return (u & 0x80000000u) ? ~u : (u | 0x80000000u);
}
__device__ __forceinline__ float funmap(unsigned u) {
    return (u & 0x80000000u) ? __uint_as_float(u & 0x7fffffffu) : __uint_as_float(~u);
}
__device__ __forceinline__ float wredsum(float v) {
#pragma unroll
    for (int o = 16; o; o >>= 1) v += __shfl_xor_sync(0xffffffffu, v, o);
    return v;
}
__device__ __forceinline__ ull pack2(float x, float y) {
    ull r; asm("mov.b64 %0, {%1,%2};" : "=l"(r) : "f"(x), "f"(y)); return r;
}
__device__ __forceinline__ void unpack2(ull v, float& x, float& y) {
    asm("mov.b64 {%0,%1}, %2;" : "=f"(x), "=f"(y) : "l"(v));
}
__device__ __forceinline__ void ffma2(ull& d, ull a, ull b) {
    asm("fma.rn.f32x2 %0, %1, %2, %0;" : "+l"(d) : "l"(a), "l"(b));
}
__device__ __forceinline__ ull fma2r(ull a, ull b, ull c) {
    ull d; asm("fma.rn.f32x2 %0, %1, %2, %3;" : "=l"(d) : "l"(a), "l"(b), "l"(c)); return d;
}
__device__ __forceinline__ ull mul2r(ull a, ull b) {
    ull d; asm("mul.rn.f32x2 %0, %1, %2;" : "=l"(d) : "l"(a), "l"(b)); return d;
}
__device__ __forceinline__ ull packh4(float a, float b, float c, float d) {
    __half2 h0 = __floats2half2_rn(a, b), h1 = __floats2half2_rn(c, d);
    uint2 u; u.x = *(unsigned*)&h0; u.y = *(unsigned*)&h1;
    return *(ull*)&u;
}
__device__ __forceinline__ unsigned smem_u32(const void* p) {
    unsigned a;
    asm("{ .reg .u64 t; cvta.to.shared.u64 t, %1; cvt.u32.u64 %0, t; }" : "=r"(a) : "l"(p));
    return a;
}

// ---------------- init ----------------
__global__ void k_init() {
    int i = blockIdx.x * 256 + threadIdx.x;
    if (i < NN) d_deg[i] = 0;
    if (i < BB * HID) {
        d_pool_sum[i] = 0.0f;
        d_pool_max[i] = fmap(-FLT_MAX);
    }
    if (i < BB) d_pool_cnt[i] = 0;
}

// node encoder: h = gelu(ln(x @ enc_w + enc_b)); writes fp32 + fp16 copies
__global__ void k_enc(const float* __restrict__ x, const float* __restrict__ W,
                      const float* __restrict__ b, const float* __restrict__ g,
                      const float* __restrict__ beta) {
    __shared__ float sW[12 * HID];
    int t = threadIdx.x;
    for (int i = t; i < 12 * HID; i += 256) sW[i] = W[i];
    __syncthreads();
    int lane = t & 31, wid = t >> 5;
    int n = blockIdx.x * 8 + wid;
    if (n >= NN) return;
    float xv[12];
#pragma unroll
    for (int k = 0; k < 12; k++) xv[k] = x[n * 12 + k];
    float v[4];
#pragma unroll
    for (int q = 0; q < 4; q++) {
        int col = q * 32 + lane;
        float s = b[col];
#pragma unroll
        for (int k = 0; k < 12; k++) s = fmaf(xv[k], sW[k * HID + col], s);
        v[q] = s;
    }
    float mean = wredsum(v[0] + v[1] + v[2] + v[3]) * (1.0f / 128.0f);
    float vs = 0.0f;
#pragma unroll
    for (int q = 0; q < 4; q++) { float d = v[q] - mean; vs += d * d; }
    vs = wredsum(vs);
    float rstd = rsqrtf(vs * (1.0f / 128.0f) + 1e-5f);
#pragma unroll
    for (int q = 0; q < 4; q++) {
        int col = q * 32 + lane;
        float y = (v[q] - mean) * rstd * g[col] + beta[col];
        float gv = gelu_f(y);
        d_h[n * HID + col] = gv;
        d_h16[n * HID + col] = __float2half(gv);
    }
}

// convert all 3 GAT linear weights to fp16
__global__ void k_w16(const float* __restrict__ Wall) {
    int i = blockIdx.x * 256 + threadIdx.x;
    if (i < LAYERS * HID * HID) d_w16[i] = __float2half(Wall[i]);
}

// ------------- tensor-core GEMM (R11 form: serialized, low regs) -----------
// block: 128 nodes x 128 cols, 8 warps; warp: 16 rows x 128 cols
__global__ void __launch_bounds__(256) k_gemm_mma(int l) {
    extern __shared__ __align__(16) char smc[];
    __half* sA = (__half*)smc;                       // 128 x STRH
    __half* sB = (__half*)(smc + 128 * STRH * 2);    // 128 x STRH
    int t = threadIdx.x, warp = t >> 5, lane = t & 31;
    int n0 = blockIdx.x * 128;
    for (int i = t; i < 128 * 16; i += 256) {
        int row = i >> 4, c = i & 15;
        int node = n0 + row;
        uint4 v = make_uint4(0u, 0u, 0u, 0u);
        if (node < NN) v = ((const uint4*)d_h16)[node * 16 + c];
        *(uint4*)(sA + row * STRH + c * 8) = v;
    }
    for (int i = t; i < 128 * 16; i += 256) {
        int row = i >> 4, c = i & 15;
        uint4 v = ((const uint4*)(d_w16 + l * HID * HID))[row * 16 + c];
        *(uint4*)(sB + row * STRH + c * 8) = v;
    }
    __syncthreads();

    float acc[16][4];
#pragma unroll
    for (int s = 0; s < 16; s++)
#pragma unroll
        for (int j = 0; j < 4; j++) acc[s][j] = 0.0f;

    unsigned baseA = smem_u32(sA) + (warp * 16 + (lane & 15)) * (STRH * 2) + (lane >> 4) * 16;
    unsigned baseB = smem_u32(sB) + (lane & 15) * (STRH * 2);

    for (int ks = 0; ks < 8; ks++) {
        unsigned a0, a1, a2, a3;
        asm volatile("ldmatrix.sync.aligned.m8n8.x4.shared.b16 {%0,%1,%2,%3}, [%4];"
                     : "=r"(a0), "=r"(a1), "=r"(a2), "=r"(a3)
                     : "r"(baseA + ks * 32));
        unsigned brow = baseB + ks * 16 * (STRH * 2);
#pragma unroll
        for (int s = 0; s < 16; s++) {
            unsigned b0, b1;
            asm volatile("ldmatrix.sync.aligned.m8n8.x2.trans.shared.b16 {%0,%1}, [%2];"
                         : "=r"(b0), "=r"(b1)
                         : "r"(brow + s * 16));
            asm volatile("mma.sync.aligned.m16n8k16.row.col.f32.f16.f16.f32 "
                         "{%0,%1,%2,%3}, {%4,%5,%6,%7}, {%8,%9}, {%0,%1,%2,%3};"
                         : "+f"(acc[s][0]), "+f"(acc[s][1]), "+f"(acc[s][2]), "+f"(acc[s][3])
                         : "r"(a0), "r"(a1), "r"(a2), "r"(a3), "r"(b0), "r"(b1));
        }
    }
    int g = lane >> 2, tq = lane & 3;
    int row0 = n0 + warp * 16 + g;
    int row1 = row0 + 8;
#pragma unroll
    for (int s = 0; s < 16; s++) {
        int col = s * 8 + tq * 2;
        if (row0 < NN) {
            __half2 h = __floats2half2_rn(acc[s][0], acc[s][1]);
            *(__half2*)&d_hhh[(size_t)row0 * HID + col] = h;
        }
        if (row1 < NN) {
            __half2 h = __floats2half2_rn(acc[s][2], acc[s][3]);
            *(__half2*)&d_hhh[(size_t)row1 * HID + col] = h;
        }
    }
}

// fp16 hh -> fp8 e4m3 copy (gather operand)
__global__ void k_hh8() {
    int i = blockIdx.x * 256 + threadIdx.x;   // 4 halves per thread
    if (i >= NN * HID / 4) return;
    ull v = ((const ull*)d_hhh)[i];
    __half2 h01 = *(__half2*)&v;
    __half2 h23 = *((__half2*)&v + 1);
    float2 f01 = __half22float2(h01), f23 = __half22float2(h23);
    unsigned short b0, b1;
    asm("cvt.rn.satfinite.e4m3x2.f32 %0, %1, %2;" : "=h"(b0) : "f"(f01.y), "f"(f01.x));
    asm("cvt.rn.satfinite.e4m3x2.f32 %0, %1, %2;" : "=h"(b1) : "f"(f23.y), "f"(f23.x));
    ((unsigned*)d_hh8)[i] = (unsigned)b0 | ((unsigned)b1 << 16);
}

// a_s/a_d dots from fp16 hh
__global__ void k_asad(const float* __restrict__ asrc, const float* __restrict__ adst, int l) {
    int t = threadIdx.x, lane = t & 31, wid = t >> 5;
    int n = blockIdx.x * 8 + wid;
    if (n >= NN) return;
    uint2 hv = *reinterpret_cast<const uint2*>(&d_hhh[(size_t)n * HID + lane * 4]);
    float2 f01 = __half22float2(*(__half2*)&hv.x);
    float2 f23 = __half22float2(*(__half2*)&hv.y);
    float4 avs = *(const float4*)&asrc[l * HID + lane * 4];
    float4 avd = *(const float4*)&adst[l * HID + lane * 4];
    float ps = f01.x * avs.x + f01.y * avs.y + f23.x * avs.z + f23.y * avs.w;
    float pd = f01.x * avd.x + f01.y * avd.y + f23.x * avd.z + f23.y * avd.w;
#pragma unroll
    for (int o = 4; o; o >>= 1) {
        ps += __shfl_xor_sync(0xffffffffu, ps, o);
        pd += __shfl_xor_sync(0xffffffffu, pd, o);
    }
    int hsel = lane >> 3;
    if ((lane & 7) == 0) {
        d_as[n * 4 + hsel] = ps;
        d_ad[n * 4 + hsel] = pd;
    }
}

// fold gat_edge_w with att_edge -> paired layout
__global__ void k_fold(const float* __restrict__ gew, const float* __restrict__ ae) {
    int t = threadIdx.x;
    if (t >= 768) return;
    int k = t / 12, o = t % 12;
    int l = o >> 2, h = o & 3;
    float s = 0.0f;
#pragma unroll
    for (int c = 0; c < 32; c++)
        s += gew[(l * 64 + k) * HID + h * 32 + c] * ae[l * HID + h * 32 + c];
    d_wepf[((k >> 1) * 12 + o) * 2 + (k & 1)] = s;
}

__global__ void k_hist(const int* __restrict__ dst) {
    int e = blockIdx.x * 256 + threadIdx.x;
    if (e < EE) atomicAdd(&d_deg[dst[e]], 1);
}

// ---------------- scan phase A ----------------
__global__ void k_scanA() {
    __shared__ int wsum[32];
    int t = threadIdx.x, lane = t & 31, wid = t >> 5;
    int i = blockIdx.x * SCAN_BLK + t;
    int v = (i < NN) ? d_deg[i] : 0;
    int x = v;
#pragma unroll
    for (int d = 1; d < 32; d <<= 1) {
        int y = __shfl_up_sync(0xffffffffu, x, d);
        if (lane >= d) x += y;
    }
    if (lane == 31) wsum[wid] = x;
    __syncthreads();
    if (wid == 0) {
        int w = wsum[lane];
#pragma unroll
        for (int d = 1; d < 32; d <<= 1) {
            int y = __shfl_up_sync(0xffffffffu, w, d);
            if (lane >= d) w += y;
        }
        wsum[lane] = w;
    }
    __syncthreads();
    int excl = x - v + (wid ? wsum[wid - 1] : 0);
    if (i < NN) d_off[i] = excl;
    if (t == SCAN_BLK - 1) d_btot[blockIdx.x] = excl + v;
}

// phase C (inlined phase B): add block-segment carry
__global__ void k_scanC() {
    __shared__ int sCarry;
    int b = blockIdx.x, t = threadIdx.x;
    int sb = (b * 256) >> 10;
    if (t < 32) {
        int v = 0;
        for (int j = t; j < sb; j += 32) v += d_btot[j];
        v = wredsum(v);
        if (t == 0) sCarry = v;
    }
    __syncthreads();
    int i = b * 256 + t;
    if (i < NN) {
        int o = d_off[i] + sCarry;
        d_off[i] = o;
        d_cur[i] = o;
    }
    if (b == gridDim.x - 1 && t == 0) {
        int tot = 0;
        for (int j = 0; j < NSB; j++) tot += d_btot[j];
        d_off[NN] = tot;
    }
}

// ---------------- scatter eattr + src into CSR order ----------------
__global__ void k_escatter(const float* __restrict__ eattr,
                           const int* __restrict__ src, const int* __restrict__ dst) {
    int e = blockIdx.x * 256 + threadIdx.x;
    if (e >= EE) return;
    float4 xa = ((const float4*)eattr)[e];
    int s = src[e], d = dst[e];
    int pos = atomicAdd(&d_cur[d], 1);
    d_csr_src[pos] = s;
    d_ea[pos] = xa;
}

// ---------------- per-edge alpha_pre (CSR order) ----------
__global__ void k_edgefeat() {
    int e = blockIdx.x * 256 + threadIdx.x;
    if (e >= EE) return;
    float4 xa = d_ea[e];
    ull xx = pack2(xa.x, xa.x), xy = pack2(xa.y, xa.y);
    ull xz = pack2(xa.z, xa.z), xw = pack2(xa.w, xa.w);
    const ull C3 = pack2(-1.18732823e-3f, -1.18732823e-3f);
    const ull C2 = pack2(9.97355701e-3f, 9.97355701e-3f);
    const ull C1 = pack2(-6.64903801e-2f, -6.64903801e-2f);
    const ull C0 = pack2(3.98942280e-1f, 3.98942280e-1f);
    const ull H05 = pack2(0.5f, 0.5f);
    const ull* W2 = reinterpret_cast<const ull*>(c_eew);
    const ull* B2 = reinterpret_cast<const ull*>(c_eeb);
    ull P[12];
#pragma unroll
    for (int o = 0; o < 12; o++) P[o] = 0ull;
#pragma unroll 4
    for (int kp = 0; kp < 32; kp++) {
        ull acc = fma2r(xx, W2[kp], B2[kp]);
        acc = fma2r(xy, W2[32 + kp], acc);
        acc = fma2r(xz, W2[64 + kp], acc);
        acc = fma2r(xw, W2[96 + kp], acc);
        ull s2 = mul2r(acc, acc);
        ull q = fma2r(s2, C3, C2);
        q = fma2r(q, s2, C1);
        q = fma2r(q, s2, C0);
        ull tt = mul2r(s2, acc);
        ull hx = mul2r(acc, H05);
        ull g2 = fma2r(tt, q, hx);
        const ull* wp = c_wep + kp * 12;
#pragma unroll
        for (int o = 0; o < 12; o++) ffma2(P[o], g2, wp[o]);
    }
    float f[12];
#pragma unroll
    for (int o = 0; o < 12; o++) {
        float lo, hi; unpack2(P[o], lo, hi); f[o] = lo + hi;
    }
    ((ull*)d_pre0)[e] = packh4(f[0], f[1], f[2], f[3]);
    ((ull*)d_pre1)[e] = packh4(f[4], f[5], f[6], f[7]);
    ((ull*)d_pre2)[e] = packh4(f[8], f[9], f[10], f[11]);
}

// per-node mean of alpha_pre (self-loop contribution)
__global__ void k_looppre() {
    int t = threadIdx.x, lane = t & 31, wid = t >> 5;
    int n = blockIdx.x * 8 + wid;
    if (n >= NN) return;
    int beg = d_off[n], end = d_off[n + 1];
    float acc[12];
#pragma unroll
    for (int o = 0; o < 12; o++) acc[o] = 0.0f;
    for (int i = beg + lane; i < end; i += 32) {
        uint2 u0 = *reinterpret_cast<const uint2*>(d_pre0 + (size_t)i * 4);
        uint2 u1 = *reinterpret_cast<const uint2*>(d_pre1 + (size_t)i * 4);
        uint2 u2 = *reinterpret_cast<const uint2*>(d_pre2 + (size_t)i * 4);
        float2 a = __half22float2(*(__half2*)&u0.x), b = __half22float2(*(__half2*)&u0.y);
        float2 c = __half22float2(*(__half2*)&u1.x), d = __half22float2(*(__half2*)&u1.y);
        float2 e = __half22float2(*(__half2*)&u2.x), g = __half22float2(*(__half2*)&u2.y);
        acc[0] += a.x; acc[1] += a.y; acc[2]  += b.x; acc[3]  += b.y;
        acc[4] += c.x; acc[5] += c.y; acc[6]  += d.x; acc[7]  += d.y;
        acc[8] += e.x; acc[9] += e.y; acc[10] += g.x; acc[11] += g.y;
    }
#pragma unroll
    for (int o = 0; o < 12; o++) acc[o] = wredsum(acc[o]);
    float inv = 1.0f / (float)max(end - beg, 1);
    if (lane == 0) {
        d_loop[0 * NN + n] = make_float4(acc[0] * inv, acc[1] * inv, acc[2] * inv, acc[3] * inv);
        d_loop[1 * NN + n] = make_float4(acc[4] * inv, acc[5] * inv, acc[6] * inv, acc[7] * inv);
        d_loop[2 * NN + n] = make_float4(acc[8] * inv, acc[9] * inv, acc[10] * inv, acc[11] * inv);
    }
}

// GAT layer: packed (src, q) smem staging, fp8 gather + HFMA2 aggregation,
// single-pass softmax with end normalization, residual + LayerNorm
__global__ void k_gat(int l, const float* __restrict__ bias,
                      const float* __restrict__ ng, const float* __restrict__ nb) {
    __shared__ __align__(16) ull s_e[8 * 132];   // [warp][h*33 + j]
    const __half* __restrict__ pre = (l == 0) ? d_pre0 : (l == 1) ? d_pre1 : d_pre2;
    int t = threadIdx.x, lane = t & 31, wid = t >> 5;
    int n = blockIdx.x * 8 + wid;
    if (n >= NN) return;
    ull* se = s_e + wid * 132;
    int beg = d_off[n], end = d_off[n + 1];
    float4 ad = *(const float4*)&d_ad[n * 4];
    float4 asn = *(const float4*)&d_as[n * 4];
    float4 lp = d_loop[l * NN + n];
    float a0 = asn.x + ad.x + lp.x; a0 = a0 > 0.f ? a0 : 0.2f * a0;
    float a1 = asn.y + ad.y + lp.y; a1 = a1 > 0.f ? a1 : 0.2f * a1;
    float a2 = asn.z + ad.z + lp.z; a2 = a2 > 0.f ? a2 : 0.2f * a2;
    float a3 = asn.w + ad.w + lp.w; a3 = a3 > 0.f ? a3 : 0.2f * a3;
    float ps0 = __expf(a0), ps1 = __expf(a1), ps2 = __expf(a2), ps3 = __expf(a3);
    int hsel = lane >> 3;
    float psel = hsel < 2 ? (hsel == 0 ? ps0 : ps1) : (hsel == 2 ? ps2 : ps3);
    // self term from fp16 hh (accurate)
    uint2 hrw = *reinterpret_cast<const uint2*>(&d_hhh[(size_t)n * HID + lane * 4]);
    __half2 ph = __float2half2_rn(psel);
    __half2 acc01 = __hmul2(ph, *(__half2*)&hrw.x);
    __half2 acc23 = __hmul2(ph, *(__half2*)&hrw.y);
    float sl0 = 0.f, sl1 = 0.f, sl2 = 0.f, sl3 = 0.f;

    for (int base = beg; base < end; base += 32) {
        int i = base + lane;
        if (i < end) {
            int srcv = d_csr_src[i];
            float4 as = *(const float4*)&d_as[srcv * 4];
            uint2 pr = *reinterpret_cast<const uint2*>(pre + (size_t)i * 4);
            float2 pa = __half22float2(*(__half2*)&pr.x);
            float2 pb = __half22float2(*(__half2*)&pr.y);
            float b0 = as.x + ad.x + pa.x; b0 = b0 > 0.f ? b0 : 0.2f * b0;
            float b1 = as.y + ad.y + pa.y; b1 = b1 > 0.f ? b1 : 0.2f * b1;
            float b2 = as.z + ad.z + pb.x; b2 = b2 > 0.f ? b2 : 0.2f * b2;
            float b3 = as.w + ad.w + pb.y; b3 = b3 > 0.f ? b3 : 0.2f * b3;
            float p0 = __expf(b0), p1 = __expf(b1), p2 = __expf(b2), p3 = __expf(b3);
            sl0 += p0; sl1 += p1; sl2 += p2; sl3 += p3;
            __half2 q0 = __float2half2_rn(p0), q1 = __float2half2_rn(p1);
            __half2 q2 = __float2half2_rn(p2), q3 = __float2half2_rn(p3);
            ull sv = (ull)(unsigned)srcv;
            se[0 * 33 + lane] = sv | ((ull)(*(unsigned*)&q0) << 32);
            se[1 * 33 + lane] = sv | ((ull)(*(unsigned*)&q1) << 32);
            se[2 * 33 + lane] = sv | ((ull)(*(unsigned*)&q2) << 32);
            se[3 * 33 + lane] = sv | ((ull)(*(unsigned*)&q3) << 32);
        }
        __syncwarp();
        int cnt = min(32, end - base);
        const ull* sel = se + hsel * 33;
#pragma unroll 4
        for (int j = 0; j < cnt; j++) {
            uint2 v = *(const uint2*)&sel[j];
            int sj = (int)v.x;
            __half2 q2v = *(__half2*)&v.y;
            unsigned u = *reinterpret_cast<const unsigned*>(&d_hh8[(size_t)sj * HID + lane * 4]);
            unsigned short w0 = (unsigned short)u, w1 = (unsigned short)(u >> 16);
            unsigned g01, g23;
            asm("cvt.rn.f16x2.e4m3x2 %0, %1;" : "=r"(g01) : "h"(w0));
            asm("cvt.rn.f16x2.e4m3x2 %0, %1;" : "=r"(g23) : "h"(w1));
            acc01 = __hfma2(q2v, *(__half2*)&g01, acc01);
            acc23 = __hfma2(q2v, *(__half2*)&g23, acc23);
        }
        __syncwarp();
    }
    sl0 = wredsum(sl0); sl1 = wredsum(sl1); sl2 = wredsum(sl2); sl3 = wredsum(sl3);
    float den = hsel < 2 ? (hsel == 0 ? sl0 + ps0 : sl1 + ps1)
                         : (hsel == 2 ? sl2 + ps2 : sl3 + ps3);
    float inv = 1.0f / (den + 1e-16f);
    float2 A01 = __half22float2(acc01);
    float2 A23 = __half22float2(acc23);

    int c0 = lane * 4;
    float4 hres = *(const float4*)&d_h[n * HID + c0];
    float4 bl = *(const float4*)&bias[l * HID + c0];
    float v0 = hres.x + A01.x * inv + bl.x;
    float v1 = hres.y + A01.y * inv + bl.y;
    float v2 = hres.z + A23.x * inv + bl.z;
    float v3 = hres.w + A23.y * inv + bl.w;
    float mean = wredsum(v0 + v1 + v2 + v3) * (1.0f / 128.0f);
    float e0 = v0 - mean, e1 = v1 - mean, e2 = v2 - mean, e3 = v3 - mean;
    float var = wredsum(e0 * e0 + e1 * e1 + e2 * e2 + e3 * e3) * (1.0f / 128.0f);
    float rstd = rsqrtf(var + 1e-5f);
    float4 gl = *(const float4*)&ng[l * HID + c0];
    float4 bb = *(const float4*)&nb[l * HID + c0];
    float4 outv;
    outv.x = e0 * rstd * gl.x + bb.x;
    outv.y = e1 * rstd * gl.y + bb.y;
    outv.z = e2 * rstd * gl.z + bb.z;
    outv.w = e3 * rstd * gl.w + bb.w;
    *(float4*)&d_h[n * HID + c0] = outv;
    *(ull*)&d_h16[n * HID + c0] = packh4(outv.x, outv.y, outv.z, outv.w);
}

// batch pooling: mean + max (batch is sorted)
__global__ void k_pool(const int* __restrict__ batch) {
    int b = blockIdx.x, s = blockIdx.y, j = threadIdx.x;
    int lo = 0, hi = NN;
    while (lo < hi) { int mid = (lo + hi) >> 1; if (batch[mid] < b) lo = mid + 1; else hi = mid; }
    int lo_b = lo;
    lo = 0; hi = NN;
    while (lo < hi) { int mid = (lo + hi) >> 1; if (batch[mid] < b + 1) lo = mid + 1; else hi = mid; }
    int hi_b = lo;
    int len = hi_b - lo_b;
    if (s == 0 && j == 0) d_pool_cnt[b] = len;
    int per = (len + 31) / 32;
    int st = lo_b + s * per, en = min(st + per, hi_b);
    if (st >= en) return;
    float sm = 0.0f, mx = -FLT_MAX;
    for (int node = st; node < en; node++) {
        float v = d_h[node * HID + j];
        sm += v;
        mx = fmaxf(mx, v);
    }
    atomicAdd(&d_pool_sum[b * HID + j], sm);
    atomicMax(&d_pool_max[b * HID + j], fmap(mx));
}

// final MLP head
__global__ void k_mlp(const float* __restrict__ w1, const float* __restrict__ b1,
                      const float* __restrict__ w2, const float* __restrict__ b2,
                      const float* __restrict__ cw1, const float* __restrict__ cb1,
                      const float* __restrict__ cw2, const float* __restrict__ cb2,
                      float* __restrict__ out) {
    __shared__ float g[256], z1[128], z2[64], z3[64], red[64];
    int b = blockIdx.x, j = threadIdx.x;
    int cnt = d_pool_cnt[b];
    {
        float mean = d_pool_sum[b * HID + j] / (float)max(cnt, 1);
        float mx = funmap(d_pool_max[b * HID + j]);
        if (cnt == 0) mx = 0.0f;
        g[j] = mean;
        g[HID + j] = mx;
    }
    __syncthreads();
    {
        float s = b1[j];
        for (int k = 0; k < 256; k++) s = fmaf(g[k], w1[k * 128 + j], s);
        z1[j] = gelu_f(s);
    }
    __syncthreads();
    if (j < 64) {
        float s = b2[j];
        for (int k = 0; k < 128; k++) s = fmaf(z1[k], w2[k * 64 + j], s);
        z2[j] = gelu_f(s);
    }
    __syncthreads();
    if (j < 64) {
        float s = cb1[j];
        for (int k = 0; k < 64; k++) s = fmaf(z2[k], cw1[k * 64 + j], s);
        z3[j] = gelu_f(s);
    }
    __syncthreads();
    if (j < 64) red[j] = z3[j] * cw2[j];
    __syncthreads();
    if (j == 0) {
        float lg = cb2[0];
        for (int k = 0; k < 64; k++) lg += red[k];
        out[b] = 1.0f / (1.0f + expf(-lg));
    }
}

// ---------------- launch ----------------
extern "C" void kernel_launch(void* const* d_in, const int* in_sizes, int n_in,
                              void* d_out, int out_size) {
    const float* x        = (const float*)d_in[0];
    const float* eattr    = (const float*)d_in[1];
    const int*   ei       = (const int*)d_in[2];
    const int*   batch    = (const int*)d_in[3];
    const float* enc_w    = (const float*)d_in[4];
    const float* enc_b    = (const float*)d_in[5];
    const float* enc_g    = (const float*)d_in[6];
    const float* enc_beta = (const float*)d_in[7];
    const float* ee_w     = (const float*)d_in[8];
    const float* ee_b     = (const float*)d_in[9];
    const float* glw      = (const float*)d_in[10];
    const float* gew      = (const float*)d_in[11];
    const float* a_src    = (const float*)d_in[12];
    const float* a_dst    = (const float*)d_in[13];
    const float* a_edge   = (const float*)d_in[14];
    const float* g_bias   = (const float*)d_in[15];
    const float* norm_g   = (const float*)d_in[16];
    const float* norm_b   = (const float*)d_in[17];
    const float* fw1      = (const float*)d_in[18];
    const float* fb1      = (const float*)d_in[19];
    const float* fw2      = (const float*)d_in[20];
    const float* fb2      = (const float*)d_in[21];
    const float* cw1      = (const float*)d_in[22];
    const float* cb1      = (const float*)d_in[23];
    const float* cw2      = (const float*)d_in[24];
    const float* cb2      = (const float*)d_in[25];
    const int* src = ei;
    const int* dst = ei + EE;
    float* out = (float*)d_out;

    const int MMA_SMEM = 2 * 128 * STRH * 2;  // 69632 B
    cudaFuncSetAttribute(k_gemm_mma, cudaFuncAttributeMaxDynamicSharedMemorySize, MMA_SMEM);

    int nwarp_blocks = (NN + 7) / 8;   // 6250
    int mma_blocks = (NN + 127) / 128; // 391
    int hh8_blocks = (NN * HID / 4 + 255) / 256;

    cudaMemcpyToSymbolAsync(c_eew, ee_w, 256 * sizeof(float), 0, cudaMemcpyDeviceToDevice);
    cudaMemcpyToSymbolAsync(c_eeb, ee_b, 64 * sizeof(float), 0, cudaMemcpyDeviceToDevice);

    k_init<<<(NN + 255) / 256, 256>>>();                              // 1
    k_enc<<<nwarp_blocks, 256>>>(x, enc_w, enc_b, enc_g, enc_beta);   // 2
    k_w16<<<(LAYERS * HID * HID + 255) / 256, 256>>>(glw);            // 3
    k_gemm_mma<<<mma_blocks, 256, MMA_SMEM>>>(0);                     // 4 (profiled)
    k_hh8<<<hh8_blocks, 256>>>();
    k_asad<<<nwarp_blocks, 256>>>(a_src, a_dst, 0);
    k_fold<<<1, 768>>>(gew, a_edge);

    void* wePtr = nullptr;
    cudaGetSymbolAddress(&wePtr, d_wepf);
    cudaMemcpyToSymbolAsync(c_wep, wePtr, 768 * sizeof(float), 0, cudaMemcpyDeviceToDevice);

    k_hist<<<(EE + 255) / 256, 256>>>(dst);
    k_scanA<<<NSB, SCAN_BLK>>>();
    k_scanC<<<(NN + 255) / 256, 256>>>();
    k_escatter<<<(EE + 255) / 256, 256>>>(eattr, src, dst);
    k_edgefeat<<<(EE + 255) / 256, 256>>>();
    k_looppre<<<nwarp_blocks, 256>>>();

    k_gat<<<nwarp_blocks, 256>>>(0, g_bias, norm_g, norm_b);
    for (int l = 1; l < LAYERS; l++) {
        k_gemm_mma<<<mma_blocks, 256, MMA_SMEM>>>(l);
        k_hh8<<<hh8_blocks, 256>>>();
        k_asad<<<nwarp_blocks, 256>>>(a_src, a_dst, l);
        k_gat<<<nwarp_blocks, 256>>>(l, g_bias, norm_g, norm_b);
    }

    dim3 pg(BB, 32);
    k_pool<<<pg, 128>>>(batch);
    k_mlp<<<BB, 128>>>(fw1, fb1, fw2, fb2, cw1, cb1, cw2, cb2, out);
}

// round 15
// speedup vs baseline: 1.1015x; 1.1015x over previous
#include <cuda_runtime.h>
#include <cuda_fp16.h>
#include <math.h>
#include <float.h>

#define NN 50000
#define EE 1600000
#define BB 64
#define HID 128
#define LAYERS 3
#define SCAN_BLK 1024
#define NSB ((NN + SCAN_BLK - 1) / SCAN_BLK)
#define STRH 136   // padded smem row stride in halves (272B); cols 128..135 = folded as/ad

typedef unsigned long long ull;

// ---------------- device scratch ----------------
__device__ __align__(256) float  d_h[NN * HID];
__device__ __align__(256) __half d_h16[NN * HID];
__device__ __align__(256) __half d_hhh[NN * HID];
__device__ __align__(256) __half d_w16[LAYERS * HID * HID];
__device__ __align__(16)  __half d_wsd[LAYERS * 128 * 8];   // [l][k][j] j:0-3 ws, 4-7 wd
__device__ __align__(16)  float  d_as[NN * 4];
__device__ __align__(16)  float  d_ad[NN * 4];
__device__ __align__(256) __half d_pre0[EE * 4];
__device__ __align__(256) __half d_pre1[EE * 4];
__device__ __align__(256) __half d_pre2[EE * 4];
__device__ __align__(256) float4 d_ea[EE];
__device__ __align__(16)  float4 d_loop[LAYERS * NN];
__device__ int d_deg[NN];
__device__ int d_off[NN + 1];
__device__ int d_cur[NN];
__device__ int d_csr_src[EE];
__device__ int d_btot[NSB];
__device__ __align__(16) float d_wepf[768];
__device__ float d_pool_sum[BB * HID];
__device__ unsigned d_pool_max[BB * HID];
__device__ int d_pool_cnt[BB];

__constant__ __align__(16) float c_eew[256];
__constant__ __align__(16) float c_eeb[64];
__constant__ __align__(16) ull   c_wep[32 * 12];

// ---------------- helpers ----------------
__device__ __forceinline__ float gelu_f(float x) {
    return 0.5f * x * (1.0f + erff(x * 0.70710678118654752f));
}
__device__ __forceinline__ unsigned fmap(float f) {
    unsigned u = __float_as_uint(f);
    return (u & 0x80000000u) ? ~u : (u | 0x80000000u);
}
__device__ __forceinline__ float funmap(unsigned u) {
    return (u & 0x80000000u) ? __uint_as_float(u & 0x7fffffffu) : __uint_as_float(~u);
}
__device__ __forceinline__ float wredsum(float v) {
#pragma unroll
    for (int o = 16; o; o >>= 1) v += __shfl_xor_sync(0xffffffffu, v, o);
    return v;
}
__device__ __forceinline__ ull pack2(float x, float y) {
    ull r; asm("mov.b64 %0, {%1,%2};" : "=l"(r) : "f"(x), "f"(y)); return r;
}
__device__ __forceinline__ void unpack2(ull v, float& x, float& y) {
    asm("mov.b64 {%0,%1}, %2;" : "=f"(x), "=f"(y) : "l"(v));
}
__device__ __forceinline__ void ffma2(ull& d, ull a, ull b) {
    asm("fma.rn.f32x2 %0, %1, %2, %0;" : "+l"(d) : "l"(a), "l"(b));
}
__device__ __forceinline__ ull fma2r(ull a, ull b, ull c) {
    ull d; asm("fma.rn.f32x2 %0, %1, %2, %3;" : "=l"(d) : "l"(a), "l"(b), "l"(c)); return d;
}
__device__ __forceinline__ ull mul2r(ull a, ull b) {
    ull d; asm("mul.rn.f32x2 %0, %1, %2;" : "=l"(d) : "l"(a), "l"(b)); return d;
}
__device__ __forceinline__ ull packh4(float a, float b, float c, float d) {
    __half2 h0 = __floats2half2_rn(a, b), h1 = __floats2half2_rn(c, d);
    uint2 u; u.x = *(unsigned*)&h0; u.y = *(unsigned*)&h1;
    return *(ull*)&u;
}
__device__ __forceinline__ unsigned smem_u32(const void* p) {
    unsigned a;
    asm("{ .reg .u64 t; cvta.to.shared.u64 t, %1; cvt.u32.u64 %0, t; }" : "=r"(a) : "l"(p));
    return a;
}

// ---------------- init ----------------
__global__ void k_init() {
    int i = blockIdx.x * 256 + threadIdx.x;
    if (i < NN) d_deg[i] = 0;
    if (i < BB * HID) {
        d_pool_sum[i] = 0.0f;
        d_pool_max[i] = fmap(-FLT_MAX);
    }
    if (i < BB) d_pool_cnt[i] = 0;
}

// node encoder: h = gelu(ln(x @ enc_w + enc_b)); writes fp32 + fp16 copies
__global__ void k_enc(const float* __restrict__ x, const float* __restrict__ W,
                      const float* __restrict__ b, const float* __restrict__ g,
                      const float* __restrict__ beta) {
    __shared__ float sW[12 * HID];
    int t = threadIdx.x;
    for (int i = t; i < 12 * HID; i += 256) sW[i] = W[i];
    __syncthreads();
    int lane = t & 31, wid = t >> 5;
    int n = blockIdx.x * 8 + wid;
    if (n >= NN) return;
    float xv[12];
#pragma unroll
    for (int k = 0; k < 12; k++) xv[k] = x[n * 12 + k];
    float v[4];
#pragma unroll
    for (int q = 0; q < 4; q++) {
        int col = q * 32 + lane;
        float s = b[col];
#pragma unroll
        for (int k = 0; k < 12; k++) s = fmaf(xv[k], sW[k * HID + col], s);
        v[q] = s;
    }
    float mean = wredsum(v[0] + v[1] + v[2] + v[3]) * (1.0f / 128.0f);
    float vs = 0.0f;
#pragma unroll
    for (int q = 0; q < 4; q++) { float d = v[q] - mean; vs += d * d; }
    vs = wredsum(vs);
    float rstd = rsqrtf(vs * (1.0f / 128.0f) + 1e-5f);
#pragma unroll
    for (int q = 0; q < 4; q++) {
        int col = q * 32 + lane;
        float y = (v[q] - mean) * rstd * g[col] + beta[col];
        float gv = gelu_f(y);
        d_h[n * HID + col] = gv;
        d_h16[n * HID + col] = __float2half(gv);
    }
}

// convert all 3 GAT linear weights to fp16
__global__ void k_w16(const float* __restrict__ Wall) {
    int i = blockIdx.x * 256 + threadIdx.x;
    if (i < LAYERS * HID * HID) d_w16[i] = __float2half(Wall[i]);
}

// fold W with att_src/att_dst: ws[l][k][h] = sum_c W[l][k][h*32+c]*att_src[l][h][c]
__global__ void k_foldsd(const float* __restrict__ Wall,
                         const float* __restrict__ asrc, const float* __restrict__ adst) {
    int t = blockIdx.x * 256 + threadIdx.x;   // LAYERS*128*8 = 3072
    if (t >= LAYERS * 128 * 8) return;
    int l = t >> 10, r = (t >> 3) & 127, j = t & 7;
    int h = j & 3;
    const float* av = (j < 4 ? asrc : adst) + l * HID + h * 32;
    const float* wr = Wall + (l * HID + r) * HID + h * 32;
    float s = 0.0f;
#pragma unroll
    for (int c = 0; c < 32; c++) s += wr[c] * av[c];
    d_wsd[(l * 128 + r) * 8 + j] = __float2half(s);
}

// ------------- tensor-core GEMM, a_s/a_d fused as extra B columns -----------
// block: 128 nodes x (128+8) cols, 8 warps; warp: 16 rows
__global__ void __launch_bounds__(256) k_gemm_mma(int l) {
    extern __shared__ __align__(16) char smc[];
    __half* sA = (__half*)smc;                       // 128 x STRH
    __half* sB = (__half*)(smc + 128 * STRH * 2);    // 128 x STRH (cols 128..135 = wsd)
    int t = threadIdx.x, warp = t >> 5, lane = t & 31;
    int n0 = blockIdx.x * 128;
    for (int i = t; i < 128 * 16; i += 256) {
        int row = i >> 4, c = i & 15;
        int node = n0 + row;
        uint4 v = make_uint4(0u, 0u, 0u, 0u);
        if (node < NN) v = ((const uint4*)d_h16)[node * 16 + c];
        *(uint4*)(sA + row * STRH + c * 8) = v;
    }
    for (int i = t; i < 128 * 16; i += 256) {
        int row = i >> 4, c = i & 15;
        uint4 v = ((const uint4*)(d_w16 + l * HID * HID))[row * 16 + c];
        *(uint4*)(sB + row * STRH + c * 8) = v;
    }
    if (t < 128)
        *(uint4*)(sB + t * STRH + 128) = ((const uint4*)d_wsd)[l * 128 + t];
    __syncthreads();

    float acc[17][4];
#pragma unroll
    for (int s = 0; s < 17; s++)
#pragma unroll
        for (int j = 0; j < 4; j++) acc[s][j] = 0.0f;

    unsigned baseA = smem_u32(sA) + (warp * 16 + (lane & 15)) * (STRH * 2) + (lane >> 4) * 16;
    unsigned baseB = smem_u32(sB) + (lane & 15) * (STRH * 2);

    for (int ks = 0; ks < 8; ks++) {
        unsigned a0, a1, a2, a3;
        asm volatile("ldmatrix.sync.aligned.m8n8.x4.shared.b16 {%0,%1,%2,%3}, [%4];"
                     : "=r"(a0), "=r"(a1), "=r"(a2), "=r"(a3)
                     : "r"(baseA + ks * 32));
        unsigned brow = baseB + ks * 16 * (STRH * 2);
#pragma unroll
        for (int s = 0; s < 17; s++) {
            unsigned b0, b1;
            asm volatile("ldmatrix.sync.aligned.m8n8.x2.trans.shared.b16 {%0,%1}, [%2];"
                         : "=r"(b0), "=r"(b1)
                         : "r"(brow + s * 16));
            asm volatile("mma.sync.aligned.m16n8k16.row.col.f32.f16.f16.f32 "
                         "{%0,%1,%2,%3}, {%4,%5,%6,%7}, {%8,%9}, {%0,%1,%2,%3};"
                         : "+f"(acc[s][0]), "+f"(acc[s][1]), "+f"(acc[s][2]), "+f"(acc[s][3])
                         : "r"(a0), "r"(a1), "r"(a2), "r"(a3), "r"(b0), "r"(b1));
        }
    }
    int g = lane >> 2, tq = lane & 3;
    int row0 = n0 + warp * 16 + g;
    int row1 = row0 + 8;
#pragma unroll
    for (int s = 0; s < 16; s++) {
        int col = s * 8 + tq * 2;
        if (row0 < NN) {
            __half2 h = __floats2half2_rn(acc[s][0], acc[s][1]);
            *(__half2*)&d_hhh[(size_t)row0 * HID + col] = h;
        }
        if (row1 < NN) {
            __half2 h = __floats2half2_rn(acc[s][2], acc[s][3]);
            *(__half2*)&d_hhh[(size_t)row1 * HID + col] = h;
        }
    }
    // tile 16: cols 128..135 = (ws h0..h3, wd h0..h3) dots
    {
        float2 e0 = make_float2(acc[16][0], acc[16][1]);
        float2 e1 = make_float2(acc[16][2], acc[16][3]);
        if (tq < 2) {
            if (row0 < NN) *(float2*)&d_as[row0 * 4 + tq * 2] = e0;
            if (row1 < NN) *(float2*)&d_as[row1 * 4 + tq * 2] = e1;
        } else {
            if (row0 < NN) *(float2*)&d_ad[row0 * 4 + (tq - 2) * 2] = e0;
            if (row1 < NN) *(float2*)&d_ad[row1 * 4 + (tq - 2) * 2] = e1;
        }
    }
}

// fold gat_edge_w with att_edge -> paired layout
__global__ void k_fold(const float* __restrict__ gew, const float* __restrict__ ae) {
    int t = threadIdx.x;
    if (t >= 768) return;
    int k = t / 12, o = t % 12;
    int l = o >> 2, h = o & 3;
    float s = 0.0f;
#pragma unroll
    for (int c = 0; c < 32; c++)
        s += gew[(l * 64 + k) * HID + h * 32 + c] * ae[l * HID + h * 32 + c];
    d_wepf[((k >> 1) * 12 + o) * 2 + (k & 1)] = s;
}

__global__ void k_hist(const int* __restrict__ dst) {
    int e = blockIdx.x * 256 + threadIdx.x;
    if (e < EE) atomicAdd(&d_deg[dst[e]], 1);
}

// ---------------- scan phase A ----------------
__global__ void k_scanA() {
    __shared__ int wsum[32];
    int t = threadIdx.x, lane = t & 31, wid = t >> 5;
    int i = blockIdx.x * SCAN_BLK + t;
    int v = (i < NN) ? d_deg[i] : 0;
    int x = v;
#pragma unroll
    for (int d = 1; d < 32; d <<= 1) {
        int y = __shfl_up_sync(0xffffffffu, x, d);
        if (lane >= d) x += y;
    }
    if (lane == 31) wsum[wid] = x;
    __syncthreads();
    if (wid == 0) {
        int w = wsum[lane];
#pragma unroll
        for (int d = 1; d < 32; d <<= 1) {
            int y = __shfl_up_sync(0xffffffffu, w, d);
            if (lane >= d) w += y;
        }
        wsum[lane] = w;
    }
    __syncthreads();
    int excl = x - v + (wid ? wsum[wid - 1] : 0);
    if (i < NN) d_off[i] = excl;
    if (t == SCAN_BLK - 1) d_btot[blockIdx.x] = excl + v;
}

// phase C (inlined phase B): add block-segment carry
__global__ void k_scanC() {
    __shared__ int sCarry;
    int b = blockIdx.x, t = threadIdx.x;
    int sb = (b * 256) >> 10;
    if (t < 32) {
        int v = 0;
        for (int j = t; j < sb; j += 32) v += d_btot[j];
        v = wredsum(v);
        if (t == 0) sCarry = v;
    }
    __syncthreads();
    int i = b * 256 + t;
    if (i < NN) {
        int o = d_off[i] + sCarry;
        d_off[i] = o;
        d_cur[i] = o;
    }
    if (b == gridDim.x - 1 && t == 0) {
        int tot = 0;
        for (int j = 0; j < NSB; j++) tot += d_btot[j];
        d_off[NN] = tot;
    }
}

// ---------------- scatter eattr + src into CSR order ----------------
__global__ void k_escatter(const float* __restrict__ eattr,
                           const int* __restrict__ src, const int* __restrict__ dst) {
    int e = blockIdx.x * 256 + threadIdx.x;
    if (e >= EE) return;
    float4 xa = ((const float4*)eattr)[e];
    int s = src[e], d = dst[e];
    int pos = atomicAdd(&d_cur[d], 1);
    d_csr_src[pos] = s;
    d_ea[pos] = xa;
}

// ---------------- per-edge alpha_pre (CSR order) ----------
__global__ void k_edgefeat() {
    int e = blockIdx.x * 256 + threadIdx.x;
    if (e >= EE) return;
    float4 xa = d_ea[e];
    ull xx = pack2(xa.x, xa.x), xy = pack2(xa.y, xa.y);
    ull xz = pack2(xa.z, xa.z), xw = pack2(xa.w, xa.w);
    const ull C3 = pack2(-1.18732823e-3f, -1.18732823e-3f);
    const ull C2 = pack2(9.97355701e-3f, 9.97355701e-3f);
    const ull C1 = pack2(-6.64903801e-2f, -6.64903801e-2f);
    const ull C0 = pack2(3.98942280e-1f, 3.98942280e-1f);
    const ull H05 = pack2(0.5f, 0.5f);
    const ull* W2 = reinterpret_cast<const ull*>(c_eew);
    const ull* B2 = reinterpret_cast<const ull*>(c_eeb);
    ull P[12];
#pragma unroll
    for (int o = 0; o < 12; o++) P[o] = 0ull;
#pragma unroll 4
    for (int kp = 0; kp < 32; kp++) {
        ull acc = fma2r(xx, W2[kp], B2[kp]);
        acc = fma2r(xy, W2[32 + kp], acc);
        acc = fma2r(xz, W2[64 + kp], acc);
        acc = fma2r(xw, W2[96 + kp], acc);
        ull s2 = mul2r(acc, acc);
        ull q = fma2r(s2, C3, C2);
        q = fma2r(q, s2, C1);
        q = fma2r(q, s2, C0);
        ull tt = mul2r(s2, acc);
        ull hx = mul2r(acc, H05);
        ull g2 = fma2r(tt, q, hx);
        const ull* wp = c_wep + kp * 12;
#pragma unroll
        for (int o = 0; o < 12; o++) ffma2(P[o], g2, wp[o]);
    }
    float f[12];
#pragma unroll
    for (int o = 0; o < 12; o++) {
        float lo, hi; unpack2(P[o], lo, hi); f[o] = lo + hi;
    }
    ((ull*)d_pre0)[e] = packh4(f[0], f[1], f[2], f[3]);
    ((ull*)d_pre1)[e] = packh4(f[4], f[5], f[6], f[7]);
    ((ull*)d_pre2)[e] = packh4(f[8], f[9], f[10], f[11]);
}

// per-node mean of alpha_pre (self-loop contribution)
__global__ void k_looppre() {
    int t = threadIdx.x, lane = t & 31, wid = t >> 5;
    int n = blockIdx.x * 8 + wid;
    if (n >= NN) return;
    int beg = d_off[n], end = d_off[n + 1];
    float acc[12];
#pragma unroll
    for (int o = 0; o < 12; o++) acc[o] = 0.0f;
    for (int i = beg + lane; i < end; i += 32) {
        uint2 u0 = *reinterpret_cast<const uint2*>(d_pre0 + (size_t)i * 4);
        uint2 u1 = *reinterpret_cast<const uint2*>(d_pre1 + (size_t)i * 4);
        uint2 u2 = *reinterpret_cast<const uint2*>(d_pre2 + (size_t)i * 4);
        float2 a = __half22float2(*(__half2*)&u0.x), b = __half22float2(*(__half2*)&u0.y);
        float2 c = __half22float2(*(__half2*)&u1.x), d = __half22float2(*(__half2*)&u1.y);
        float2 e = __half22float2(*(__half2*)&u2.x), g = __half22float2(*(__half2*)&u2.y);
        acc[0] += a.x; acc[1] += a.y; acc[2]  += b.x; acc[3]  += b.y;
        acc[4] += c.x; acc[5] += c.y; acc[6]  += d.x; acc[7]  += d.y;
        acc[8] += e.x; acc[9] += e.y; acc[10] += g.x; acc[11] += g.y;
    }
#pragma unroll
    for (int o = 0; o < 12; o++) acc[o] = wredsum(acc[o]);
    float inv = 1.0f / (float)max(end - beg, 1);
    if (lane == 0) {
        d_loop[0 * NN + n] = make_float4(acc[0] * inv, acc[1] * inv, acc[2] * inv, acc[3] * inv);
        d_loop[1 * NN + n] = make_float4(acc[4] * inv, acc[5] * inv, acc[6] * inv, acc[7] * inv);
        d_loop[2 * NN + n] = make_float4(acc[8] * inv, acc[9] * inv, acc[10] * inv, acc[11] * inv);
    }
}

// GAT layer: packed (src, q) smem staging, fp16 gather + HFMA2 aggregation,
// single-pass softmax with end normalization, residual + LayerNorm
__global__ void k_gat(int l, const float* __restrict__ bias,
                      const float* __restrict__ ng, const float* __restrict__ nb) {
    __shared__ __align__(16) ull s_e[8 * 132];   // [warp][h*33 + j]
    const __half* __restrict__ pre = (l == 0) ? d_pre0 : (l == 1) ? d_pre1 : d_pre2;
    int t = threadIdx.x, lane = t & 31, wid = t >> 5;
    int n = blockIdx.x * 8 + wid;
    if (n >= NN) return;
    ull* se = s_e + wid * 132;
    int beg = d_off[n], end = d_off[n + 1];
    float4 ad = *(const float4*)&d_ad[n * 4];
    float4 asn = *(const float4*)&d_as[n * 4];
    float4 lp = d_loop[l * NN + n];
    float a0 = asn.x + ad.x + lp.x; a0 = a0 > 0.f ? a0 : 0.2f * a0;
    float a1 = asn.y + ad.y + lp.y; a1 = a1 > 0.f ? a1 : 0.2f * a1;
    float a2 = asn.z + ad.z + lp.z; a2 = a2 > 0.f ? a2 : 0.2f * a2;
    float a3 = asn.w + ad.w + lp.w; a3 = a3 > 0.f ? a3 : 0.2f * a3;
    float ps0 = __expf(a0), ps1 = __expf(a1), ps2 = __expf(a2), ps3 = __expf(a3);
    int hsel = lane >> 3;
    float psel = hsel < 2 ? (hsel == 0 ? ps0 : ps1) : (hsel == 2 ? ps2 : ps3);
    uint2 hrw = *reinterpret_cast<const uint2*>(&d_hhh[(size_t)n * HID + lane * 4]);
    __half2 ph = __float2half2_rn(psel);
    __half2 acc01 = __hmul2(ph, *(__half2*)&hrw.x);
    __half2 acc23 = __hmul2(ph, *(__half2*)&hrw.y);
    float sl0 = 0.f, sl1 = 0.f, sl2 = 0.f, sl3 = 0.f;

    for (int base = beg; base < end; base += 32) {
        int i = base + lane;
        if (i < end) {
            int srcv = d_csr_src[i];
            float4 as = *(const float4*)&d_as[srcv * 4];
            uint2 pr = *reinterpret_cast<const uint2*>(pre + (size_t)i * 4);
            float2 pa = __half22float2(*(__half2*)&pr.x);
            float2 pb = __half22float2(*(__half2*)&pr.y);
            float b0 = as.x + ad.x + pa.x; b0 = b0 > 0.f ? b0 : 0.2f * b0;
            float b1 = as.y + ad.y + pa.y; b1 = b1 > 0.f ? b1 : 0.2f * b1;
            float b2 = as.z + ad.z + pb.x; b2 = b2 > 0.f ? b2 : 0.2f * b2;
            float b3 = as.w + ad.w + pb.y; b3 = b3 > 0.f ? b3 : 0.2f * b3;
            float p0 = __expf(b0), p1 = __expf(b1), p2 = __expf(b2), p3 = __expf(b3);
            sl0 += p0; sl1 += p1; sl2 += p2; sl3 += p3;
            __half2 q0 = __float2half2_rn(p0), q1 = __float2half2_rn(p1);
            __half2 q2 = __float2half2_rn(p2), q3 = __float2half2_rn(p3);
            ull sv = (ull)(unsigned)srcv;
            se[0 * 33 + lane] = sv | ((ull)(*(unsigned*)&q0) << 32);
            se[1 * 33 + lane] = sv | ((ull)(*(unsigned*)&q1) << 32);
            se[2 * 33 + lane] = sv | ((ull)(*(unsigned*)&q2) << 32);
            se[3 * 33 + lane] = sv | ((ull)(*(unsigned*)&q3) << 32);
        }
        __syncwarp();
        int cnt = min(32, end - base);
        const ull* sel = se + hsel * 33;
#pragma unroll 4
        for (int j = 0; j < cnt; j++) {
            uint2 v = *(const uint2*)&sel[j];
            int sj = (int)v.x;
            __half2 q2v = *(__half2*)&v.y;
            uint2 h2 = *reinterpret_cast<const uint2*>(&d_hhh[(size_t)sj * HID + lane * 4]);
            acc01 = __hfma2(q2v, *(__half2*)&h2.x, acc01);
            acc23 = __hfma2(q2v, *(__half2*)&h2.y, acc23);
        }
        __syncwarp();
    }
    sl0 = wredsum(sl0); sl1 = wredsum(sl1); sl2 = wredsum(sl2); sl3 = wredsum(sl3);
    float den = hsel < 2 ? (hsel == 0 ? sl0 + ps0 : sl1 + ps1)
                         : (hsel == 2 ? sl2 + ps2 : sl3 + ps3);
    float inv = 1.0f / (den + 1e-16f);
    float2 A01 = __half22float2(acc01);
    float2 A23 = __half22float2(acc23);

    int c0 = lane * 4;
    float4 hres = *(const float4*)&d_h[n * HID + c0];
    float4 bl = *(const float4*)&bias[l * HID + c0];
    float v0 = hres.x + A01.x * inv + bl.x;
    float v1 = hres.y + A01.y * inv + bl.y;
    float v2 = hres.z + A23.x * inv + bl.z;
    float v3 = hres.w + A23.y * inv + bl.w;
    float mean = wredsum(v0 + v1 + v2 + v3) * (1.0f / 128.0f);
    float e0 = v0 - mean, e1 = v1 - mean, e2 = v2 - mean, e3 = v3 - mean;
    float var = wredsum(e0 * e0 + e1 * e1 + e2 * e2 + e3 * e3) * (1.0f / 128.0f);
    float rstd = rsqrtf(var + 1e-5f);
    float4 gl = *(const float4*)&ng[l * HID + c0];
    float4 bb = *(const float4*)&nb[l * HID + c0];
    float4 outv;
    outv.x = e0 * rstd * gl.x + bb.x;
    outv.y = e1 * rstd * gl.y + bb.y;
    outv.z = e2 * rstd * gl.z + bb.z;
    outv.w = e3 * rstd * gl.w + bb.w;
    *(float4*)&d_h[n * HID + c0] = outv;
    *(ull*)&d_h16[n * HID + c0] = packh4(outv.x, outv.y, outv.z, outv.w);
}

// batch pooling: mean + max (batch is sorted)
__global__ void k_pool(const int* __restrict__ batch) {
    int b = blockIdx.x, s = blockIdx.y, j = threadIdx.x;
    int lo = 0, hi = NN;
    while (lo < hi) { int mid = (lo + hi) >> 1; if (batch[mid] < b) lo = mid + 1; else hi = mid; }
    int lo_b = lo;
    lo = 0; hi = NN;
    while (lo < hi) { int mid = (lo + hi) >> 1; if (batch[mid] < b + 1) lo = mid + 1; else hi = mid; }
    int hi_b = lo;
    int len = hi_b - lo_b;
    if (s == 0 && j == 0) d_pool_cnt[b] = len;
    int per = (len + 31) / 32;
    int st = lo_b + s * per, en = min(st + per, hi_b);
    if (st >= en) return;
    float sm = 0.0f, mx = -FLT_MAX;
    for (int node = st; node < en; node++) {
        float v = d_h[node * HID + j];
        sm += v;
        mx = fmaxf(mx, v);
    }
    atomicAdd(&d_pool_sum[b * HID + j], sm);
    atomicMax(&d_pool_max[b * HID + j], fmap(mx));
}

// final MLP head
__global__ void k_mlp(const float* __restrict__ w1, const float* __restrict__ b1,
                      const float* __restrict__ w2, const float* __restrict__ b2,
                      const float* __restrict__ cw1, const float* __restrict__ cb1,
                      const float* __restrict__ cw2, const float* __restrict__ cb2,
                      float* __restrict__ out) {
    __shared__ float g[256], z1[128], z2[64], z3[64], red[64];
    int b = blockIdx.x, j = threadIdx.x;
    int cnt = d_pool_cnt[b];
    {
        float mean = d_pool_sum[b * HID + j] / (float)max(cnt, 1);
        float mx = funmap(d_pool_max[b * HID + j]);
        if (cnt == 0) mx = 0.0f;
        g[j] = mean;
        g[HID + j] = mx;
    }
    __syncthreads();
    {
        float s = b1[j];
        for (int k = 0; k < 256; k++) s = fmaf(g[k], w1[k * 128 + j], s);
        z1[j] = gelu_f(s);
    }
    __syncthreads();
    if (j < 64) {
        float s = b2[j];
        for (int k = 0; k < 128; k++) s = fmaf(z1[k], w2[k * 64 + j], s);
        z2[j] = gelu_f(s);
    }
    __syncthreads();
    if (j < 64) {
        float s = cb1[j];
        for (int k = 0; k < 64; k++) s = fmaf(z2[k], cw1[k * 64 + j], s);
        z3[j] = gelu_f(s);
    }
    __syncthreads();
    if (j < 64) red[j] = z3[j] * cw2[j];
    __syncthreads();
    if (j == 0) {
        float lg = cb2[0];
        for (int k = 0; k < 64; k++) lg += red[k];
        out[b] = 1.0f / (1.0f + expf(-lg));
    }
}

// ---------------- launch ----------------
extern "C" void kernel_launch(void* const* d_in, const int* in_sizes, int n_in,
                              void* d_out, int out_size) {
    const float* x        = (const float*)d_in[0];
    const float* eattr    = (const float*)d_in[1];
    const int*   ei       = (const int*)d_in[2];
    const int*   batch    = (const int*)d_in[3];
    const float* enc_w    = (const float*)d_in[4];
    const float* enc_b    = (const float*)d_in[5];
    const float* enc_g    = (const float*)d_in[6];
    const float* enc_beta = (const float*)d_in[7];
    const float* ee_w     = (const float*)d_in[8];
    const float* ee_b     = (const float*)d_in[9];
    const float* glw      = (const float*)d_in[10];
    const float* gew      = (const float*)d_in[11];
    const float* a_src    = (const float*)d_in[12];
    const float* a_dst    = (const float*)d_in[13];
    const float* a_edge   = (const float*)d_in[14];
    const float* g_bias   = (const float*)d_in[15];
    const float* norm_g   = (const float*)d_in[16];
    const float* norm_b   = (const float*)d_in[17];
    const float* fw1      = (const float*)d_in[18];
    const float* fb1      = (const float*)d_in[19];
    const float* fw2      = (const float*)d_in[20];
    const float* fb2      = (const float*)d_in[21];
    const float* cw1      = (const float*)d_in[22];
    const float* cb1      = (const float*)d_in[23];
    const float* cw2      = (const float*)d_in[24];
    const float* cb2      = (const float*)d_in[25];
    const int* src = ei;
    const int* dst = ei + EE;
    float* out = (float*)d_out;

    const int MMA_SMEM = 2 * 128 * STRH * 2;  // 69632 B
    cudaFuncSetAttribute(k_gemm_mma, cudaFuncAttributeMaxDynamicSharedMemorySize, MMA_SMEM);

    int nwarp_blocks = (NN + 7) / 8;   // 6250
    int mma_blocks = (NN + 127) / 128; // 391

    // stream + events, created once on the first (non-captured) correctness call
    static cudaStream_t s1 = nullptr;
    static cudaEvent_t ev_fork = nullptr, ev_join = nullptr;
    if (s1 == nullptr) {
        cudaStreamCreateWithFlags(&s1, cudaStreamNonBlocking);
        cudaEventCreateWithFlags(&ev_fork, cudaEventDisableTiming);
        cudaEventCreateWithFlags(&ev_join, cudaEventDisableTiming);
    }

    cudaMemcpyToSymbolAsync(c_eew, ee_w, 256 * sizeof(float), 0, cudaMemcpyDeviceToDevice);
    cudaMemcpyToSymbolAsync(c_eeb, ee_b, 64 * sizeof(float), 0, cudaMemcpyDeviceToDevice);
    k_init<<<(NN + 255) / 256, 256>>>();

    // fork node pipeline onto s1
    cudaEventRecord(ev_fork, 0);
    cudaStreamWaitEvent(s1, ev_fork, 0);
    k_enc<<<nwarp_blocks, 256, 0, s1>>>(x, enc_w, enc_b, enc_g, enc_beta);
    k_w16<<<(LAYERS * HID * HID + 255) / 256, 256, 0, s1>>>(glw);
    k_foldsd<<<(LAYERS * 128 * 8 + 255) / 256, 256, 0, s1>>>(glw, a_src, a_dst);
    k_gemm_mma<<<mma_blocks, 256, MMA_SMEM, s1>>>(0);
    cudaEventRecord(ev_join, s1);

    // edge pipeline on default stream
    k_fold<<<1, 768>>>(gew, a_edge);
    void* wePtr = nullptr;
    cudaGetSymbolAddress(&wePtr, d_wepf);
    cudaMemcpyToSymbolAsync(c_wep, wePtr, 768 * sizeof(float), 0, cudaMemcpyDeviceToDevice);
    k_hist<<<(EE + 255) / 256, 256>>>(dst);
    k_scanA<<<NSB, SCAN_BLK>>>();
    k_scanC<<<(NN + 255) / 256, 256>>>();
    k_escatter<<<(EE + 255) / 256, 256>>>(eattr, src, dst);
    k_edgefeat<<<(EE + 255) / 256, 256>>>();
    k_looppre<<<nwarp_blocks, 256>>>();

    // join
    cudaStreamWaitEvent(0, ev_join, 0);

    k_gat<<<nwarp_blocks, 256>>>(0, g_bias, norm_g, norm_b);
    for (int l = 1; l < LAYERS; l++) {
        k_gemm_mma<<<mma_blocks, 256, MMA_SMEM>>>(l);
        k_gat<<<nwarp_blocks, 256>>>(l, g_bias, norm_g, norm_b);
    }

    dim3 pg(BB, 32);
    k_pool<<<pg, 128>>>(batch);
    k_mlp<<<BB, 128>>>(fw1, fb1, fw2, fb2, cw1, cb1, cw2, cb2, out);
}

// round 16
// speedup vs baseline: 1.1506x; 1.0445x over previous
#include <cuda_runtime.h>
#include <cuda_fp16.h>
#include <math.h>
#include <float.h>

#define NN 50000
#define EE 1600000
#define BB 64
#define HID 128
#define LAYERS 3
#define SCAN_BLK 1024
#define NSB ((NN + SCAN_BLK - 1) / SCAN_BLK)
#define STRH 136   // padded smem row stride in halves (272B); cols 128..135 = folded as/ad

typedef unsigned long long ull;

// ---------------- device scratch ----------------
__device__ __align__(256) float  d_h[NN * HID];
__device__ __align__(256) __half d_h16[NN * HID];
__device__ __align__(256) __half d_hhh[NN * HID];
__device__ __align__(256) __half d_w16[LAYERS * HID * HID];
__device__ __align__(16)  __half d_wsd[LAYERS * 128 * 8];   // [l][k][j] j:0-3 ws, 4-7 wd
__device__ __align__(16)  float  d_as[NN * 4];
__device__ __align__(16)  float  d_ad[NN * 4];
__device__ __align__(256) __half d_pre0[EE * 4];
__device__ __align__(256) __half d_pre1[EE * 4];
__device__ __align__(256) __half d_pre2[EE * 4];
__device__ __align__(16)  float4 d_loop[LAYERS * NN];
__device__ int d_deg[NN];
__device__ int d_off[NN + 1];
__device__ int d_cur[NN];
__device__ int d_csr_src[EE];
__device__ int d_btot[NSB];
__device__ __align__(16) float d_wepf[768];
__device__ float d_pool_sum[BB * HID];
__device__ unsigned d_pool_max[BB * HID];
__device__ int d_pool_cnt[BB];

__constant__ __align__(16) float c_eew[256];
__constant__ __align__(16) float c_eeb[64];
__constant__ __align__(16) ull   c_wep[32 * 12];

// ---------------- helpers ----------------
__device__ __forceinline__ float gelu_f(float x) {
    return 0.5f * x * (1.0f + erff(x * 0.70710678118654752f));
}
__device__ __forceinline__ unsigned fmap(float f) {
    unsigned u = __float_as_uint(f);
    return (u & 0x80000000u) ? ~u : (u | 0x80000000u);
}
__device__ __forceinline__ float funmap(unsigned u) {
    return (u & 0x80000000u) ? __uint_as_float(u & 0x7fffffffu) : __uint_as_float(~u);
}
__device__ __forceinline__ float wredsum(float v) {
#pragma unroll
    for (int o = 16; o; o >>= 1) v += __shfl_xor_sync(0xffffffffu, v, o);
    return v;
}
__device__ __forceinline__ ull pack2(float x, float y) {
    ull r; asm("mov.b64 %0, {%1,%2};" : "=l"(r) : "f"(x), "f"(y)); return r;
}
__device__ __forceinline__ void unpack2(ull v, float& x, float& y) {
    asm("mov.b64 {%0,%1}, %2;" : "=f"(x), "=f"(y) : "l"(v));
}
__device__ __forceinline__ void ffma2(ull& d, ull a, ull b) {
    asm("fma.rn.f32x2 %0, %1, %2, %0;" : "+l"(d) : "l"(a), "l"(b));
}
__device__ __forceinline__ ull fma2r(ull a, ull b, ull c) {
    ull d; asm("fma.rn.f32x2 %0, %1, %2, %3;" : "=l"(d) : "l"(a), "l"(b), "l"(c)); return d;
}
__device__ __forceinline__ ull mul2r(ull a, ull b) {
    ull d; asm("mul.rn.f32x2 %0, %1, %2;" : "=l"(d) : "l"(a), "l"(b)); return d;
}
__device__ __forceinline__ ull packh4(float a, float b, float c, float d) {
    __half2 h0 = __floats2half2_rn(a, b), h1 = __floats2half2_rn(c, d);
    uint2 u; u.x = *(unsigned*)&h0; u.y = *(unsigned*)&h1;
    return *(ull*)&u;
}
__device__ __forceinline__ unsigned smem_u32(const void* p) {
    unsigned a;
    asm("{ .reg .u64 t; cvta.to.shared.u64 t, %1; cvt.u32.u64 %0, t; }" : "=r"(a) : "l"(p));
    return a;
}

// ---------------- init ----------------
__global__ void k_init() {
    int i = blockIdx.x * 256 + threadIdx.x;
    if (i < NN) d_deg[i] = 0;
    if (i < BB * HID) {
        d_pool_sum[i] = 0.0f;
        d_pool_max[i] = fmap(-FLT_MAX);
    }
    if (i < BB) d_pool_cnt[i] = 0;
}

// node encoder: h = gelu(ln(x @ enc_w + enc_b)); writes fp32 + fp16 copies
__global__ void k_enc(const float* __restrict__ x, const float* __restrict__ W,
                      const float* __restrict__ b, const float* __restrict__ g,
                      const float* __restrict__ beta) {
    __shared__ float sW[12 * HID];
    int t = threadIdx.x;
    for (int i = t; i < 12 * HID; i += 256) sW[i] = W[i];
    __syncthreads();
    int lane = t & 31, wid = t >> 5;
    int n = blockIdx.x * 8 + wid;
    if (n >= NN) return;
    float xv[12];
#pragma unroll
    for (int k = 0; k < 12; k++) xv[k] = x[n * 12 + k];
    float v[4];
#pragma unroll
    for (int q = 0; q < 4; q++) {
        int col = q * 32 + lane;
        float s = b[col];
#pragma unroll
        for (int k = 0; k < 12; k++) s = fmaf(xv[k], sW[k * HID + col], s);
        v[q] = s;
    }
    float mean = wredsum(v[0] + v[1] + v[2] + v[3]) * (1.0f / 128.0f);
    float vs = 0.0f;
#pragma unroll
    for (int q = 0; q < 4; q++) { float d = v[q] - mean; vs += d * d; }
    vs = wredsum(vs);
    float rstd = rsqrtf(vs * (1.0f / 128.0f) + 1e-5f);
#pragma unroll
    for (int q = 0; q < 4; q++) {
        int col = q * 32 + lane;
        float y = (v[q] - mean) * rstd * g[col] + beta[col];
        float gv = gelu_f(y);
        d_h[n * HID + col] = gv;
        d_h16[n * HID + col] = __float2half(gv);
    }
}

// convert all 3 GAT linear weights to fp16
__global__ void k_w16(const float* __restrict__ Wall) {
    int i = blockIdx.x * 256 + threadIdx.x;
    if (i < LAYERS * HID * HID) d_w16[i] = __float2half(Wall[i]);
}

// fold W with att_src/att_dst: ws[l][k][h] = sum_c W[l][k][h*32+c]*att_src[l][h][c]
__global__ void k_foldsd(const float* __restrict__ Wall,
                         const float* __restrict__ asrc, const float* __restrict__ adst) {
    int t = blockIdx.x * 256 + threadIdx.x;   // LAYERS*128*8 = 3072
    if (t >= LAYERS * 128 * 8) return;
    int l = t >> 10, r = (t >> 3) & 127, j = t & 7;
    int h = j & 3;
    const float* av = (j < 4 ? asrc : adst) + l * HID + h * 32;
    const float* wr = Wall + (l * HID + r) * HID + h * 32;
    float s = 0.0f;
#pragma unroll
    for (int c = 0; c < 32; c++) s += wr[c] * av[c];
    d_wsd[(l * 128 + r) * 8 + j] = __float2half(s);
}

// ------------- tensor-core GEMM, a_s/a_d fused as extra B columns -----------
// block: 128 nodes x (128+8) cols, 8 warps; warp: 16 rows
__global__ void __launch_bounds__(256) k_gemm_mma(int l) {
    extern __shared__ __align__(16) char smc[];
    __half* sA = (__half*)smc;                       // 128 x STRH
    __half* sB = (__half*)(smc + 128 * STRH * 2);    // 128 x STRH (cols 128..135 = wsd)
    int t = threadIdx.x, warp = t >> 5, lane = t & 31;
    int n0 = blockIdx.x * 128;
    for (int i = t; i < 128 * 16; i += 256) {
        int row = i >> 4, c = i & 15;
        int node = n0 + row;
        uint4 v = make_uint4(0u, 0u, 0u, 0u);
        if (node < NN) v = ((const uint4*)d_h16)[node * 16 + c];
        *(uint4*)(sA + row * STRH + c * 8) = v;
    }
    for (int i = t; i < 128 * 16; i += 256) {
        int row = i >> 4, c = i & 15;
        uint4 v = ((const uint4*)(d_w16 + l * HID * HID))[row * 16 + c];
        *(uint4*)(sB + row * STRH + c * 8) = v;
    }
    if (t < 128)
        *(uint4*)(sB + t * STRH + 128) = ((const uint4*)d_wsd)[l * 128 + t];
    __syncthreads();

    float acc[17][4];
#pragma unroll
    for (int s = 0; s < 17; s++)
#pragma unroll
        for (int j = 0; j < 4; j++) acc[s][j] = 0.0f;

    unsigned baseA = smem_u32(sA) + (warp * 16 + (lane & 15)) * (STRH * 2) + (lane >> 4) * 16;
    unsigned baseB = smem_u32(sB) + (lane & 15) * (STRH * 2);

    for (int ks = 0; ks < 8; ks++) {
        unsigned a0, a1, a2, a3;
        asm volatile("ldmatrix.sync.aligned.m8n8.x4.shared.b16 {%0,%1,%2,%3}, [%4];"
                     : "=r"(a0), "=r"(a1), "=r"(a2), "=r"(a3)
                     : "r"(baseA + ks * 32));
        unsigned brow = baseB + ks * 16 * (STRH * 2);
#pragma unroll
        for (int s = 0; s < 17; s++) {
            unsigned b0, b1;
            asm volatile("ldmatrix.sync.aligned.m8n8.x2.trans.shared.b16 {%0,%1}, [%2];"
                         : "=r"(b0), "=r"(b1)
                         : "r"(brow + s * 16));
            asm volatile("mma.sync.aligned.m16n8k16.row.col.f32.f16.f16.f32 "
                         "{%0,%1,%2,%3}, {%4,%5,%6,%7}, {%8,%9}, {%0,%1,%2,%3};"
                         : "+f"(acc[s][0]), "+f"(acc[s][1]), "+f"(acc[s][2]), "+f"(acc[s][3])
                         : "r"(a0), "r"(a1), "r"(a2), "r"(a3), "r"(b0), "r"(b1));
        }
    }
    int g = lane >> 2, tq = lane & 3;
    int row0 = n0 + warp * 16 + g;
    int row1 = row0 + 8;
#pragma unroll
    for (int s = 0; s < 16; s++) {
        int col = s * 8 + tq * 2;
        if (row0 < NN) {
            __half2 h = __floats2half2_rn(acc[s][0], acc[s][1]);
            *(__half2*)&d_hhh[(size_t)row0 * HID + col] = h;
        }
        if (row1 < NN) {
            __half2 h = __floats2half2_rn(acc[s][2], acc[s][3]);
            *(__half2*)&d_hhh[(size_t)row1 * HID + col] = h;
        }
    }
    // tile 16: cols 128..135 = (ws h0..h3, wd h0..h3) dots
    {
        float2 e0 = make_float2(acc[16][0], acc[16][1]);
        float2 e1 = make_float2(acc[16][2], acc[16][3]);
        if (tq < 2) {
            if (row0 < NN) *(float2*)&d_as[row0 * 4 + tq * 2] = e0;
            if (row1 < NN) *(float2*)&d_as[row1 * 4 + tq * 2] = e1;
        } else {
            if (row0 < NN) *(float2*)&d_ad[row0 * 4 + (tq - 2) * 2] = e0;
            if (row1 < NN) *(float2*)&d_ad[row1 * 4 + (tq - 2) * 2] = e1;
        }
    }
}

// fold gat_edge_w with att_edge -> paired layout
__global__ void k_fold(const float* __restrict__ gew, const float* __restrict__ ae) {
    int t = threadIdx.x;
    if (t >= 768) return;
    int k = t / 12, o = t % 12;
    int l = o >> 2, h = o & 3;
    float s = 0.0f;
#pragma unroll
    for (int c = 0; c < 32; c++)
        s += gew[(l * 64 + k) * HID + h * 32 + c] * ae[l * HID + h * 32 + c];
    d_wepf[((k >> 1) * 12 + o) * 2 + (k & 1)] = s;
}

__global__ void k_hist(const int* __restrict__ dst) {
    int e = blockIdx.x * 256 + threadIdx.x;
    if (e < EE) atomicAdd(&d_deg[dst[e]], 1);
}

// ---------------- scan phase A ----------------
__global__ void k_scanA() {
    __shared__ int wsum[32];
    int t = threadIdx.x, lane = t & 31, wid = t >> 5;
    int i = blockIdx.x * SCAN_BLK + t;
    int v = (i < NN) ? d_deg[i] : 0;
    int x = v;
#pragma unroll
    for (int d = 1; d < 32; d <<= 1) {
        int y = __shfl_up_sync(0xffffffffu, x, d);
        if (lane >= d) x += y;
    }
    if (lane == 31) wsum[wid] = x;
    __syncthreads();
    if (wid == 0) {
        int w = wsum[lane];
#pragma unroll
        for (int d = 1; d < 32; d <<= 1) {
            int y = __shfl_up_sync(0xffffffffu, w, d);
            if (lane >= d) w += y;
        }
        wsum[lane] = w;
    }
    __syncthreads();
    int excl = x - v + (wid ? wsum[wid - 1] : 0);
    if (i < NN) d_off[i] = excl;
    if (t == SCAN_BLK - 1) d_btot[blockIdx.x] = excl + v;
}

// phase C (inlined phase B): add block-segment carry
__global__ void k_scanC() {
    __shared__ int sCarry;
    int b = blockIdx.x, t = threadIdx.x;
    int sb = (b * 256) >> 10;
    if (t < 32) {
        int v = 0;
        for (int j = t; j < sb; j += 32) v += d_btot[j];
        v = wredsum(v);
        if (t == 0) sCarry = v;
    }
    __syncthreads();
    int i = b * 256 + t;
    if (i < NN) {
        int o = d_off[i] + sCarry;
        d_off[i] = o;
        d_cur[i] = o;
    }
    if (b == gridDim.x - 1 && t == 0) {
        int tot = 0;
        for (int j = 0; j < NSB; j++) tot += d_btot[j];
        d_off[NN] = tot;
    }
}

// ---------------- fused: per-edge alpha_pre compute + CSR scatter -----------
// reads eattr sequentially, computes 12 folded logits (f32x2), scatters
// src + 3x8B fp16 packs to the CSR position. No d_ea staging.
__global__ void k_edgescatter(const float* __restrict__ eattr,
                              const int* __restrict__ src, const int* __restrict__ dst) {
    int e = blockIdx.x * 256 + threadIdx.x;
    if (e >= EE) return;
    float4 xa = ((const float4*)eattr)[e];
    ull xx = pack2(xa.x, xa.x), xy = pack2(xa.y, xa.y);
    ull xz = pack2(xa.z, xa.z), xw = pack2(xa.w, xa.w);
    const ull C3 = pack2(-1.18732823e-3f, -1.18732823e-3f);
    const ull C2 = pack2(9.97355701e-3f, 9.97355701e-3f);
    const ull C1 = pack2(-6.64903801e-2f, -6.64903801e-2f);
    const ull C0 = pack2(3.98942280e-1f, 3.98942280e-1f);
    const ull H05 = pack2(0.5f, 0.5f);
    const ull* W2 = reinterpret_cast<const ull*>(c_eew);
    const ull* B2 = reinterpret_cast<const ull*>(c_eeb);
    ull P[12];
#pragma unroll
    for (int o = 0; o < 12; o++) P[o] = 0ull;
#pragma unroll 4
    for (int kp = 0; kp < 32; kp++) {
        ull acc = fma2r(xx, W2[kp], B2[kp]);
        acc = fma2r(xy, W2[32 + kp], acc);
        acc = fma2r(xz, W2[64 + kp], acc);
        acc = fma2r(xw, W2[96 + kp], acc);
        ull s2 = mul2r(acc, acc);
        ull q = fma2r(s2, C3, C2);
        q = fma2r(q, s2, C1);
        q = fma2r(q, s2, C0);
        ull tt = mul2r(s2, acc);
        ull hx = mul2r(acc, H05);
        ull g2 = fma2r(tt, q, hx);
        const ull* wp = c_wep + kp * 12;
#pragma unroll
        for (int o = 0; o < 12; o++) ffma2(P[o], g2, wp[o]);
    }
    float f[12];
#pragma unroll
    for (int o = 0; o < 12; o++) {
        float lo, hi; unpack2(P[o], lo, hi); f[o] = lo + hi;
    }
    int d = dst[e], s = src[e];
    int pos = atomicAdd(&d_cur[d], 1);
    d_csr_src[pos] = s;
    ((ull*)d_pre0)[pos] = packh4(f[0], f[1], f[2], f[3]);
    ((ull*)d_pre1)[pos] = packh4(f[4], f[5], f[6], f[7]);
    ((ull*)d_pre2)[pos] = packh4(f[8], f[9], f[10], f[11]);
}

// per-node mean of alpha_pre (self-loop contribution)
__global__ void k_looppre() {
    int t = threadIdx.x, lane = t & 31, wid = t >> 5;
    int n = blockIdx.x * 8 + wid;
    if (n >= NN) return;
    int beg = d_off[n], end = d_off[n + 1];
    float acc[12];
#pragma unroll
    for (int o = 0; o < 12; o++) acc[o] = 0.0f;
    for (int i = beg + lane; i < end; i += 32) {
        uint2 u0 = *reinterpret_cast<const uint2*>(d_pre0 + (size_t)i * 4);
        uint2 u1 = *reinterpret_cast<const uint2*>(d_pre1 + (size_t)i * 4);
        uint2 u2 = *reinterpret_cast<const uint2*>(d_pre2 + (size_t)i * 4);
        float2 a = __half22float2(*(__half2*)&u0.x), b = __half22float2(*(__half2*)&u0.y);
        float2 c = __half22float2(*(__half2*)&u1.x), d = __half22float2(*(__half2*)&u1.y);
        float2 e = __half22float2(*(__half2*)&u2.x), g = __half22float2(*(__half2*)&u2.y);
        acc[0] += a.x; acc[1] += a.y; acc[2]  += b.x; acc[3]  += b.y;
        acc[4] += c.x; acc[5] += c.y; acc[6]  += d.x; acc[7]  += d.y;
        acc[8] += e.x; acc[9] += e.y; acc[10] += g.x; acc[11] += g.y;
    }
#pragma unroll
    for (int o = 0; o < 12; o++) acc[o] = wredsum(acc[o]);
    float inv = 1.0f / (float)max(end - beg, 1);
    if (lane == 0) {
        d_loop[0 * NN + n] = make_float4(acc[0] * inv, acc[1] * inv, acc[2] * inv, acc[3] * inv);
        d_loop[1 * NN + n] = make_float4(acc[4] * inv, acc[5] * inv, acc[6] * inv, acc[7] * inv);
        d_loop[2 * NN + n] = make_float4(acc[8] * inv, acc[9] * inv, acc[10] * inv, acc[11] * inv);
    }
}

// GAT layer: packed (src, q) smem staging, fp16 gather + HFMA2 aggregation,
// single-pass softmax with end normalization, residual + LayerNorm
__global__ void k_gat(int l, const float* __restrict__ bias,
                      const float* __restrict__ ng, const float* __restrict__ nb) {
    __shared__ __align__(16) ull s_e[8 * 132];   // [warp][h*33 + j]
    const __half* __restrict__ pre = (l == 0) ? d_pre0 : (l == 1) ? d_pre1 : d_pre2;
    int t = threadIdx.x, lane = t & 31, wid = t >> 5;
    int n = blockIdx.x * 8 + wid;
    if (n >= NN) return;
    ull* se = s_e + wid * 132;
    int beg = d_off[n], end = d_off[n + 1];
    float4 ad = *(const float4*)&d_ad[n * 4];
    float4 asn = *(const float4*)&d_as[n * 4];
    float4 lp = d_loop[l * NN + n];
    float a0 = asn.x + ad.x + lp.x; a0 = a0 > 0.f ? a0 : 0.2f * a0;
    float a1 = asn.y + ad.y + lp.y; a1 = a1 > 0.f ? a1 : 0.2f * a1;
    float a2 = asn.z + ad.z + lp.z; a2 = a2 > 0.f ? a2 : 0.2f * a2;
    float a3 = asn.w + ad.w + lp.w; a3 = a3 > 0.f ? a3 : 0.2f * a3;
    float ps0 = __expf(a0), ps1 = __expf(a1), ps2 = __expf(a2), ps3 = __expf(a3);
    int hsel = lane >> 3;
    float psel = hsel < 2 ? (hsel == 0 ? ps0 : ps1) : (hsel == 2 ? ps2 : ps3);
    uint2 hrw = *reinterpret_cast<const uint2*>(&d_hhh[(size_t)n * HID + lane * 4]);
    __half2 ph = __float2half2_rn(psel);
    __half2 acc01 = __hmul2(ph, *(__half2*)&hrw.x);
    __half2 acc23 = __hmul2(ph, *(__half2*)&hrw.y);
    float sl0 = 0.f, sl1 = 0.f, sl2 = 0.f, sl3 = 0.f;

    for (int base = beg; base < end; base += 32) {
        int i = base + lane;
        if (i < end) {
            int srcv = d_csr_src[i];
            float4 as = *(const float4*)&d_as[srcv * 4];
            uint2 pr = *reinterpret_cast<const uint2*>(pre + (size_t)i * 4);
            float2 pa = __half22float2(*(__half2*)&pr.x);
            float2 pb = __half22float2(*(__half2*)&pr.y);
            float b0 = as.x + ad.x + pa.x; b0 = b0 > 0.f ? b0 : 0.2f * b0;
            float b1 = as.y + ad.y + pa.y; b1 = b1 > 0.f ? b1 : 0.2f * b1;
            float b2 = as.z + ad.z + pb.x; b2 = b2 > 0.f ? b2 : 0.2f * b2;
            float b3 = as.w + ad.w + pb.y; b3 = b3 > 0.f ? b3 : 0.2f * b3;
            float p0 = __expf(b0), p1 = __expf(b1), p2 = __expf(b2), p3 = __expf(b3);
            sl0 += p0; sl1 += p1; sl2 += p2; sl3 += p3;
            __half2 q0 = __float2half2_rn(p0), q1 = __float2half2_rn(p1);
            __half2 q2 = __float2half2_rn(p2), q3 = __float2half2_rn(p3);
            ull sv = (ull)(unsigned)srcv;
            se[0 * 33 + lane] = sv | ((ull)(*(unsigned*)&q0) << 32);
            se[1 * 33 + lane] = sv | ((ull)(*(unsigned*)&q1) << 32);
            se[2 * 33 + lane] = sv | ((ull)(*(unsigned*)&q2) << 32);
            se[3 * 33 + lane] = sv | ((ull)(*(unsigned*)&q3) << 32);
        }
        __syncwarp();
        int cnt = min(32, end - base);
        const ull* sel = se + hsel * 33;
#pragma unroll 8
        for (int j = 0; j < cnt; j++) {
            uint2 v = *(const uint2*)&sel[j];
            int sj = (int)v.x;
            __half2 q2v = *(__half2*)&v.y;
            uint2 h2 = *reinterpret_cast<const uint2*>(&d_hhh[(size_t)sj * HID + lane * 4]);
            acc01 = __hfma2(q2v, *(__half2*)&h2.x, acc01);
            acc23 = __hfma2(q2v, *(__half2*)&h2.y, acc23);
        }
        __syncwarp();
    }
    sl0 = wredsum(sl0); sl1 = wredsum(sl1); sl2 = wredsum(sl2); sl3 = wredsum(sl3);
    float den = hsel < 2 ? (hsel == 0 ? sl0 + ps0 : sl1 + ps1)
                         : (hsel == 2 ? sl2 + ps2 : sl3 + ps3);
    float inv = 1.0f / (den + 1e-16f);
    float2 A01 = __half22float2(acc01);
    float2 A23 = __half22float2(acc23);

    int c0 = lane * 4;
    float4 hres = *(const float4*)&d_h[n * HID + c0];
    float4 bl = *(const float4*)&bias[l * HID + c0];
    float v0 = hres.x + A01.x * inv + bl.x;
    float v1 = hres.y + A01.y * inv + bl.y;
    float v2 = hres.z + A23.x * inv + bl.z;
    float v3 = hres.w + A23.y * inv + bl.w;
    float mean = wredsum(v0 + v1 + v2 + v3) * (1.0f / 128.0f);
    float e0 = v0 - mean, e1 = v1 - mean, e2 = v2 - mean, e3 = v3 - mean;
    float var = wredsum(e0 * e0 + e1 * e1 + e2 * e2 + e3 * e3) * (1.0f / 128.0f);
    float rstd = rsqrtf(var + 1e-5f);
    float4 gl = *(const float4*)&ng[l * HID + c0];
    float4 bb = *(const float4*)&nb[l * HID + c0];
    float4 outv;
    outv.x = e0 * rstd * gl.x + bb.x;
    outv.y = e1 * rstd * gl.y + bb.y;
    outv.z = e2 * rstd * gl.z + bb.z;
    outv.w = e3 * rstd * gl.w + bb.w;
    *(float4*)&d_h[n * HID + c0] = outv;
    *(ull*)&d_h16[n * HID + c0] = packh4(outv.x, outv.y, outv.z, outv.w);
}

// batch pooling: mean + max (batch is sorted)
__global__ void k_pool(const int* __restrict__ batch) {
    int b = blockIdx.x, s = blockIdx.y, j = threadIdx.x;
    int lo = 0, hi = NN;
    while (lo < hi) { int mid = (lo + hi) >> 1; if (batch[mid] < b) lo = mid + 1; else hi = mid; }
    int lo_b = lo;
    lo = 0; hi = NN;
    while (lo < hi) { int mid = (lo + hi) >> 1; if (batch[mid] < b + 1) lo = mid + 1; else hi = mid; }
    int hi_b = lo;
    int len = hi_b - lo_b;
    if (s == 0 && j == 0) d_pool_cnt[b] = len;
    int per = (len + 31) / 32;
    int st = lo_b + s * per, en = min(st + per, hi_b);
    if (st >= en) return;
    float sm = 0.0f, mx = -FLT_MAX;
    for (int node = st; node < en; node++) {
        float v = d_h[node * HID + j];
        sm += v;
        mx = fmaxf(mx, v);
    }
    atomicAdd(&d_pool_sum[b * HID + j], sm);
    atomicMax(&d_pool_max[b * HID + j], fmap(mx));
}

// final MLP head
__global__ void k_mlp(const float* __restrict__ w1, const float* __restrict__ b1,
                      const float* __restrict__ w2, const float* __restrict__ b2,
                      const float* __restrict__ cw1, const float* __restrict__ cb1,
                      const float* __restrict__ cw2, const float* __restrict__ cb2,
                      float* __restrict__ out) {
    __shared__ float g[256], z1[128], z2[64], z3[64], red[64];
    int b = blockIdx.x, j = threadIdx.x;
    int cnt = d_pool_cnt[b];
    {
        float mean = d_pool_sum[b * HID + j] / (float)max(cnt, 1);
        float mx = funmap(d_pool_max[b * HID + j]);
        if (cnt == 0) mx = 0.0f;
        g[j] = mean;
        g[HID + j] = mx;
    }
    __syncthreads();
    {
        float s = b1[j];
        for (int k = 0; k < 256; k++) s = fmaf(g[k], w1[k * 128 + j], s);
        z1[j] = gelu_f(s);
    }
    __syncthreads();
    if (j < 64) {
        float s = b2[j];
        for (int k = 0; k < 128; k++) s = fmaf(z1[k], w2[k * 64 + j], s);
        z2[j] = gelu_f(s);
    }
    __syncthreads();
    if (j < 64) {
        float s = cb1[j];
        for (int k = 0; k < 64; k++) s = fmaf(z2[k], cw1[k * 64 + j], s);
        z3[j] = gelu_f(s);
    }
    __syncthreads();
    if (j < 64) red[j] = z3[j] * cw2[j];
    __syncthreads();
    if (j == 0) {
        float lg = cb2[0];
        for (int k = 0; k < 64; k++) lg += red[k];
        out[b] = 1.0f / (1.0f + expf(-lg));
    }
}

// ---------------- launch ----------------
extern "C" void kernel_launch(void* const* d_in, const int* in_sizes, int n_in,
                              void* d_out, int out_size) {
    const float* x        = (const float*)d_in[0];
    const float* eattr    = (const float*)d_in[1];
    const int*   ei       = (const int*)d_in[2];
    const int*   batch    = (const int*)d_in[3];
    const float* enc_w    = (const float*)d_in[4];
    const float* enc_b    = (const float*)d_in[5];
    const float* enc_g    = (const float*)d_in[6];
    const float* enc_beta = (const float*)d_in[7];
    const float* ee_w     = (const float*)d_in[8];
    const float* ee_b     = (const float*)d_in[9];
    const float* glw      = (const float*)d_in[10];
    const float* gew      = (const float*)d_in[11];
    const float* a_src    = (const float*)d_in[12];
    const float* a_dst    = (const float*)d_in[13];
    const float* a_edge   = (const float*)d_in[14];
    const float* g_bias   = (const float*)d_in[15];
    const float* norm_g   = (const float*)d_in[16];
    const float* norm_b   = (const float*)d_in[17];
    const float* fw1      = (const float*)d_in[18];
    const float* fb1      = (const float*)d_in[19];
    const float* fw2      = (const float*)d_in[20];
    const float* fb2      = (const float*)d_in[21];
    const float* cw1      = (const float*)d_in[22];
    const float* cb1      = (const float*)d_in[23];
    const float* cw2      = (const float*)d_in[24];
    const float* cb2      = (const float*)d_in[25];
    const int* src = ei;
    const int* dst = ei + EE;
    float* out = (float*)d_out;

    const int MMA_SMEM = 2 * 128 * STRH * 2;  // 69632 B
    cudaFuncSetAttribute(k_gemm_mma, cudaFuncAttributeMaxDynamicSharedMemorySize, MMA_SMEM);

    int nwarp_blocks = (NN + 7) / 8;   // 6250
    int mma_blocks = (NN + 127) / 128; // 391

    // stream + events, created once on the first (non-captured) correctness call
    static cudaStream_t s1 = nullptr;
    static cudaEvent_t ev_fork = nullptr, ev_join = nullptr;
    if (s1 == nullptr) {
        cudaStreamCreateWithFlags(&s1, cudaStreamNonBlocking);
        cudaEventCreateWithFlags(&ev_fork, cudaEventDisableTiming);
        cudaEventCreateWithFlags(&ev_join, cudaEventDisableTiming);
    }

    cudaMemcpyToSymbolAsync(c_eew, ee_w, 256 * sizeof(float), 0, cudaMemcpyDeviceToDevice);
    cudaMemcpyToSymbolAsync(c_eeb, ee_b, 64 * sizeof(float), 0, cudaMemcpyDeviceToDevice);
    k_init<<<(NN + 255) / 256, 256>>>();

    // fork node pipeline onto s1
    cudaEventRecord(ev_fork, 0);
    cudaStreamWaitEvent(s1, ev_fork, 0);
    k_enc<<<nwarp_blocks, 256, 0, s1>>>(x, enc_w, enc_b, enc_g, enc_beta);
    k_w16<<<(LAYERS * HID * HID + 255) / 256, 256, 0, s1>>>(glw);
    k_foldsd<<<(LAYERS * 128 * 8 + 255) / 256, 256, 0, s1>>>(glw, a_src, a_dst);
    k_gemm_mma<<<mma_blocks, 256, MMA_SMEM, s1>>>(0);
    cudaEventRecord(ev_join, s1);

    // edge pipeline on default stream
    k_fold<<<1, 768>>>(gew, a_edge);
    void* wePtr = nullptr;
    cudaGetSymbolAddress(&wePtr, d_wepf);
    cudaMemcpyToSymbolAsync(c_wep, wePtr, 768 * sizeof(float), 0, cudaMemcpyDeviceToDevice);
    k_hist<<<(EE + 255) / 256, 256>>>(dst);
    k_scanA<<<NSB, SCAN_BLK>>>();
    k_scanC<<<(NN + 255) / 256, 256>>>();
    k_edgescatter<<<(EE + 255) / 256, 256>>>(eattr, src, dst);
    k_looppre<<<nwarp_blocks, 256>>>();

    // join
    cudaStreamWaitEvent(0, ev_join, 0);

    k_gat<<<nwarp_blocks, 256>>>(0, g_bias, norm_g, norm_b);
    for (int l = 1; l < LAYERS; l++) {
        k_gemm_mma<<<mma_blocks, 256, MMA_SMEM>>>(l);
        k_gat<<<nwarp_blocks, 256>>>(l, g_bias, norm_g, norm_b);
    }

    dim3 pg(BB, 32);
    k_pool<<<pg, 128>>>(batch);
    k_mlp<<<BB, 128>>>(fw1, fb1, fw2, fb2, cw1, cb1, cw2, cb2, out);
}